// round 15
// baseline (speedup 1.0000x reference)
#include <cuda_runtime.h>
#include <cstdint>
#include <cstddef>

#define WIDTH  2048
#define DEPTH  8
#define DP1    9
#define TMOD   242          // 30*DEPTH + 2
#define WD     16384        // WIDTH*DEPTH
#define NSPLIT 16           // i-splits for hidden
#define CHUNK  128          // WIDTH / NSPLIT
#define HBLK   256          // hidden blocks (16 kblk x 16 split)
#define CBLK   512          // contrib blocks (4 rows each)
#define WROLES (HBLK + CBLK)        // 768 = 256*3

// d_out layout (float32, reference return order)
#define OFF_OUT   0ULL
#define OFF_STATE 1ULL
#define OFF_SA    18433ULL
#define OFF_SG    4478977ULL
#define OFF_OG    4495361ULL
#define OFF_GRAD  8955905ULL
#define OFF_OWG   42510337ULL

#define N_SAOG    (WIDTH * DP1 * TMOD)     // 4460544
#define NQ_SAOG   1115135                  // quads idx = 3+4q
#define NQ_GROW   4095                     // per-row quads k = 3+4q

// saog split: first SAOG_MAIN blocks' quads in k_main, rest in grad phase
#define SAOG_MAIN 2560                     // q < 655360
#define Q_SPLIT   (SAOG_MAIN * 256)
#define SAOG_GRAD 1796                     // covers the rest (last thread=tail)
#define MAIN_BLK  (256 * 13)               // 3328: bx%13<3 -> W-role
#define GRAD_BLK  (SAOG_GRAD + WIDTH)      // 3844

// scratch (allocation-free)
__device__ float g_hpart[NSPLIT][WD];     // hidden partials (1 MB)
__device__ float g_contrib[WD];           // contrib[i*8+a], a=0..6
__device__ float g_m[WD];
__device__ float g_mshift[WD];            // g_mshift[t] = m[t+3]
__device__ float g_aprev[WD];
__device__ float g_out_acc;

__device__ __forceinline__ int posmod(int v, int m) {
    int r = v % m;
    return r < 0 ? r + m : r;
}

// ---------------------------------------------------------------------------
// MAIN: bx%13<3 -> W-role wr=(bx/13)*3+bx%13 (wr<256: hidden; else contrib
// block of 4 rows); else saog pure-copy quad block sid=(bx/13)*10+(bx%13-3)
// for q < Q_SPLIT (__ldcs/__stcs streaming; finalize fixes the time slice).
// ---------------------------------------------------------------------------
__global__ void k_main(const float* __restrict__ W,
                       const float* __restrict__ state_in,
                       const float* __restrict__ sgrad,
                       float* __restrict__ out,
                       const float* __restrict__ sa_in,
                       const float* __restrict__ og_in) {
    __shared__ float sh[CHUNK * 8];
    const int tid = threadIdx.x;
    const int bx  = blockIdx.x;
    const int lane13 = bx % 13;

    if (lane13 < 3) {
        const int wr = (bx / 13) * 3 + lane13;   // 0..767
        if (wr == 0 && tid == 0) g_out_acc = 0.f;

        if (wr < HBLK) {
            // ---- hidden partial: hidden[k] = sum_i W[i*WD+k]*state[i,k&7]
            const int kblk  = wr & 15;
            const int split = wr >> 4;
            const int k4 = kblk * 1024 + tid * 4;
            const int i0 = split * CHUNK;
            const int dbase = (tid & 1) * 4;

            for (int idx = tid; idx < CHUNK * 8; idx += 256) {
                int i = idx >> 3, d = idx & 7;
                sh[idx] = state_in[(size_t)(i0 + i) * DP1 + d];
            }
            __syncthreads();

            const float* Wp = W + (size_t)i0 * WD + k4;
            float4 acc = make_float4(0.f, 0.f, 0.f, 0.f);
#pragma unroll 8
            for (int i = 0; i < CHUNK; ++i) {
                float4 w4 = *reinterpret_cast<const float4*>(Wp + (size_t)i * WD);
                float4 sv = *reinterpret_cast<const float4*>(&sh[i * 8 + dbase]);
                acc.x = fmaf(w4.x, sv.x, acc.x);
                acc.y = fmaf(w4.y, sv.y, acc.y);
                acc.z = fmaf(w4.z, sv.z, acc.z);
                acc.w = fmaf(w4.w, sv.w, acc.w);
            }
            *reinterpret_cast<float4*>(&g_hpart[split][k4]) = acc;
        } else {
            // ---- contrib, 4 rows per block: g loaded once per j, feeds 4 rows
            const int i0 = (wr - HBLK) * 4;
            const float4* gg = reinterpret_cast<const float4*>(sgrad);
            const float4* Wr0 = reinterpret_cast<const float4*>(W + (size_t)i0 * WD);

            float acc[4][7];
#pragma unroll
            for (int r = 0; r < 4; ++r)
#pragma unroll
                for (int a = 0; a < 7; ++a) acc[r][a] = 0.f;

            for (int j = tid; j < WIDTH; j += 256) {
                float4 g0 = gg[j * 2];
                float4 g1 = gg[j * 2 + 1];
#pragma unroll
                for (int r = 0; r < 4; ++r) {
                    const float4* Wr = Wr0 + (size_t)r * (WD / 4);
                    float4 w0 = Wr[j * 2];
                    float4 w1 = Wr[j * 2 + 1];
                    acc[r][0] = fmaf(w0.y, g0.y, acc[r][0]);
                    acc[r][1] = fmaf(w0.z, g0.z, acc[r][1]);
                    acc[r][2] = fmaf(w0.w, g0.w, acc[r][2]);
                    acc[r][3] = fmaf(w1.x, g1.x, acc[r][3]);
                    acc[r][4] = fmaf(w1.y, g1.y, acc[r][4]);
                    acc[r][5] = fmaf(w1.z, g1.z, acc[r][5]);
                    acc[r][6] = fmaf(w1.w, g1.w, acc[r][6]);
                }
            }
            float (*red)[4][7] = reinterpret_cast<float (*)[4][7]>(sh);
#pragma unroll
            for (int r = 0; r < 4; ++r)
#pragma unroll
                for (int a = 0; a < 7; ++a)
#pragma unroll
                    for (int off = 16; off; off >>= 1)
                        acc[r][a] += __shfl_down_sync(0xffffffffu, acc[r][a], off);
            if ((tid & 31) == 0) {
                int wwid = tid >> 5;
#pragma unroll
                for (int r = 0; r < 4; ++r)
#pragma unroll
                    for (int a = 0; a < 7; ++a) red[wwid][r][a] = acc[r][a];
            }
            __syncthreads();
            if (tid < 28) {
                int r = tid / 7, a = tid % 7;
                float s = 0.f;
#pragma unroll
                for (int wi = 0; wi < 8; ++wi) s += red[wi][r][a];
                g_contrib[(size_t)(i0 + r) * 8 + a] = s;
            }
        }
    } else {
        // ---- saog (main part): pure copy, q < Q_SPLIT
        const int sid = (bx / 13) * 10 + (lane13 - 3);   // 0..2559
        const int q = sid * 256 + tid;
        const int idx = 3 + 4 * q;

        const float4* sa4 = reinterpret_cast<const float4*>(sa_in);
        const float4* og4 = reinterpret_cast<const float4*>(og_in);
        float4 sA = __ldcs(sa4 + q), sB = __ldcs(sa4 + q + 1);
        float4 oA = __ldcs(og4 + q), oB = __ldcs(og4 + q + 1);

        __stcs(reinterpret_cast<float4*>(&out[OFF_SA + idx]),
               make_float4(sA.w, sB.x, sB.y, sB.z));
        __stcs(reinterpret_cast<float4*>(&out[OFF_OG + idx]),
               make_float4(oA.w, oB.x, oB.y, oB.z));

        if (q == 0) {
#pragma unroll
            for (int e = 0; e < 3; ++e) {
                out[OFF_SA + e] = sa_in[e];
                out[OFF_OG + e] = og_in[e];
            }
        }
    }
#if __CUDA_ARCH__ >= 900
    cudaTriggerProgrammaticLaunchCompletion();
#endif
}

// ---------------------------------------------------------------------------
// finalize (PDL): prologue = input-only loads; sync; consume scratch + write.
// Time-slice fixup covers the k_main saog region (stale copies); grad-phase
// saog blocks do their own time check, so double-writes agree in value.
// tia(a) = time + 2a - 14 (mod 242); tia==time only at a=7, (tia±1)!=time.
// ---------------------------------------------------------------------------
__global__ void k_finalize(float* __restrict__ out,
                           const float* __restrict__ x,
                           const float* __restrict__ ow,
                           const float* __restrict__ sa_in,
                           const float* __restrict__ og_in,
                           const int* __restrict__ time_p) {
    const int k = blockIdx.x * blockDim.x + threadIdx.x;   // 0..WD-1
    const int w = k >> 3, a = k & 7;
    const int time = *time_p;

    const int tia = posmod(time - 2 * DEPTH + 2 * (a + 1), TMOD);
    float rm_v = 0.f, og_v = 0.f, rg_pre = 0.f, aprev;
    const float ow_o  = ow[(size_t)w * DP1 + a + 1];
    const float ow_o0 = (a == 0) ? ow[(size_t)w * DP1] : 0.f;
    const float xv    = (a == 0) ? x[w] : 0.f;
    if (a < DEPTH - 1) {
        int t1 = (tia + 1) % TMOD;
        rm_v = sa_in[((size_t)w * DP1 + a + 2) * TMOD + t1];
        og_v = og_in[((size_t)w * DP1 + a + 1) * TMOD + tia];
        rg_pre = sa_in[((size_t)w * DP1 + a + 1) * TMOD + tia];
        aprev = sa_in[((size_t)w * DP1 + a) * TMOD + posmod(tia - 1, TMOD)];
    } else {
        aprev = sa_in[((size_t)w * DP1 + DEPTH - 1) * TMOD + posmod(time - 1, TMOD)];
    }

#if __CUDA_ARCH__ >= 900
    cudaGridDependencySynchronize();
#endif

    float h = 0.f;
#pragma unroll
    for (int c = 0; c < NSPLIT; ++c) h += g_hpart[c][k];
    float s = fmaxf(h, 0.f);

    size_t o = (size_t)w * DP1 + a + 1;
    out[OFF_STATE + o] = s;
    out[OFF_OWG + o]   = s;
    out[OFF_SA + o * TMOD + time] = s;
    out[OFF_OG + o * TMOD + time] = ow_o;
    float v = ow_o * s;
    if (a == 0) {
        size_t o0 = (size_t)w * DP1;
        out[OFF_STATE + o0] = xv;
        out[OFF_OWG   + o0] = xv;
        out[OFF_SA + o0 * TMOD + time] = xv;
        out[OFF_OG + o0 * TMOD + time] = ow_o0;
        v = fmaf(ow_o0, xv, v);
    }

    float sgv, rg;
    if (a < DEPTH - 1) {
        sgv = fmaf(rm_v > 0.f ? 1.f : 0.f, g_contrib[k], og_v);
        rg = (rg_pre > 0.f) ? 1.f : 0.f;
    } else {
        sgv = ow[(size_t)w * DP1 + DEPTH];
        rg = (s > 0.f) ? 1.f : 0.f;
    }
    out[OFF_SG + k] = sgv;
    float mval = sgv * rg;
    g_m[k] = mval;
    if (k >= 3) g_mshift[k - 3] = mval;
    g_aprev[k] = aprev;

    __shared__ float red[8];
#pragma unroll
    for (int off = 16; off; off >>= 1)
        v += __shfl_down_sync(0xffffffffu, v, off);
    if ((threadIdx.x & 31) == 0) red[threadIdx.x >> 5] = v;
    __syncthreads();
    if (threadIdx.x == 0) {
        float t = 0.f;
#pragma unroll
        for (int i = 0; i < 8; ++i) t += red[i];
        atomicAdd(&g_out_acc, t);
    }
#if __CUDA_ARCH__ >= 900
    cudaTriggerProgrammaticLaunchCompletion();
#endif
}

// ---------------------------------------------------------------------------
// grad phase (PDL): grad rows interleaved with the remaining saog quads
// (time-aware — state is valid after the grid sync). bx<3592: even -> saog
// sid=bx/2, odd -> grad row bx/2; else grad rows 1796..2047.
// ---------------------------------------------------------------------------
__global__ void k_grad(float* __restrict__ out,
                       const float* __restrict__ sa_in,
                       const float* __restrict__ og_in,
                       const float* __restrict__ ow,
                       const int* __restrict__ time_p) {
    const int tid = threadIdx.x;
    const int bx  = blockIdx.x;

#if __CUDA_ARCH__ >= 900
    cudaGridDependencySynchronize();
#endif

    bool is_saog = (bx < 2 * SAOG_GRAD) && ((bx & 1) == 0);
    if (is_saog) {
        // ---- saog tail part with time check ----
        const int time = *time_p;
        const int q = Q_SPLIT + (bx >> 1) * 256 + tid;
        if (q >= NQ_SAOG) {
            // the single out-of-range thread handles the final element
            const int it = N_SAOG - 1;
            int tt = it % TMOD, wcc = it / TMOD;
            out[OFF_SA + it] = (tt == time) ? out[OFF_STATE + wcc] : sa_in[it];
            out[OFF_OG + it] = (tt == time) ? ow[wcc] : og_in[it];
            return;
        }
        const int idx = 3 + 4 * q;

        const float4* sa4 = reinterpret_cast<const float4*>(sa_in);
        const float4* og4 = reinterpret_cast<const float4*>(og_in);
        float4 sA = __ldcs(sa4 + q), sB = __ldcs(sa4 + q + 1);
        float4 oA = __ldcs(og4 + q), oB = __ldcs(og4 + q + 1);
        float sv[4] = {sA.w, sB.x, sB.y, sB.z};
        float ov[4] = {oA.w, oB.x, oB.y, oB.z};

        int t  = idx % TMOD;
        int wc = idx / TMOD;
#pragma unroll
        for (int e = 0; e < 4; ++e) {
            int tt = t + e, wcc = wc;
            if (tt >= TMOD) { tt -= TMOD; ++wcc; }
            if (tt == time) {
                sv[e] = out[OFF_STATE + wcc];
                ov[e] = ow[wcc];
            }
        }
        __stcs(reinterpret_cast<float4*>(&out[OFF_SA + idx]),
               make_float4(sv[0], sv[1], sv[2], sv[3]));
        __stcs(reinterpret_cast<float4*>(&out[OFF_OG + idx]),
               make_float4(ov[0], ov[1], ov[2], ov[3]));
    } else {
        // ---- grad row ----
        const int i = (bx < 2 * SAOG_GRAD) ? (bx >> 1)
                                           : (bx - 2 * SAOG_GRAD + SAOG_GRAD);
        if (i == 0 && tid == 0) out[OFF_OUT] = g_out_acc;

        const float* ap = g_aprev + (size_t)i * 8;
        const float4 apv = (tid & 1)
            ? make_float4(__ldg(ap + 7), __ldg(ap + 0), __ldg(ap + 1), __ldg(ap + 2))
            : make_float4(__ldg(ap + 3), __ldg(ap + 4), __ldg(ap + 5), __ldg(ap + 6));

        float* dst = out + OFF_GRAD + (size_t)i * WD;
        const float4* ms4 = reinterpret_cast<const float4*>(g_mshift);

        for (int q = tid; q < NQ_GROW; q += 256) {
            float4 mv = ms4[q];
            __stcs(reinterpret_cast<float4*>(dst + 3 + 4 * q),
                   make_float4(apv.x * mv.x, apv.y * mv.y,
                               apv.z * mv.z, apv.w * mv.w));
        }
        if (tid == 0) {
            dst[0] = __ldg(ap + 0) * g_m[0];
            dst[1] = __ldg(ap + 1) * g_m[1];
            dst[2] = __ldg(ap + 2) * g_m[2];
        } else if (tid == 1) {
            dst[WD - 1] = __ldg(ap + 7) * g_m[WD - 1];
        }
    }
}

// ---------------------------------------------------------------------------
extern "C" void kernel_launch(void* const* d_in, const int* in_sizes, int n_in,
                              void* d_out, int out_size) {
    const float* x    = (const float*)d_in[0];
    const float* W    = (const float*)d_in[1];
    const float* ow   = (const float*)d_in[2];
    const float* st   = (const float*)d_in[3];
    const float* sa   = (const float*)d_in[4];
    const float* sgr  = (const float*)d_in[5];
    const float* og   = (const float*)d_in[6];
    const int*   tim  = (const int*)d_in[7];
    float* out = (float*)d_out;

    k_main<<<MAIN_BLK, 256>>>(W, st, sgr, out, sa, og);

    cudaLaunchAttribute attr[1];
    attr[0].id = cudaLaunchAttributeProgrammaticStreamSerialization;
    attr[0].val.programmaticStreamSerializationAllowed = 1;

    {
        cudaLaunchConfig_t cfg = {};
        cfg.gridDim = dim3(WD / 256);
        cfg.blockDim = dim3(256);
        cfg.attrs = attr;
        cfg.numAttrs = 1;
        cudaLaunchKernelEx(&cfg, k_finalize, out, x, ow, sa, og, tim);
    }
    {
        cudaLaunchConfig_t cfg = {};
        cfg.gridDim = dim3(GRAD_BLK);
        cfg.blockDim = dim3(256);
        cfg.attrs = attr;
        cfg.numAttrs = 1;
        cudaLaunchKernelEx(&cfg, k_grad, out, sa, og, ow, tim);
    }
}

// round 16
// speedup vs baseline: 1.0245x; 1.0245x over previous
#include <cuda_runtime.h>
#include <cstdint>
#include <cstddef>

#define WIDTH  2048
#define DEPTH  8
#define DP1    9
#define TMOD   242          // 30*DEPTH + 2
#define WD     16384        // WIDTH*DEPTH
#define NSPLIT 16           // i-splits for hidden
#define CHUNK  128          // WIDTH / NSPLIT
#define HBLK   256          // hidden blocks (16 kblk x 16 split)
#define CBLK   512          // contrib blocks (4 rows each)
#define WROLES (HBLK + CBLK)        // 768
#define MAIN_BLK (WROLES * 7)       // 5376: bx%7==0 -> W-role, else saog

// d_out layout (float32, reference return order)
#define OFF_OUT   0ULL
#define OFF_STATE 1ULL
#define OFF_SA    18433ULL
#define OFF_SG    4478977ULL
#define OFF_OG    4495361ULL
#define OFF_GRAD  8955905ULL
#define OFF_OWG   42510337ULL

#define N_SAOG    (WIDTH * DP1 * TMOD)     // 4460544
#define NQ_SAOG   1115135                  // quads idx = 3+4q
#define NQ_GROW   4095                     // per-row quads k = 3+4q

// scratch (allocation-free)
__device__ float g_hpart[NSPLIT][WD];     // hidden partials (1 MB)
__device__ float g_contrib[WD];           // contrib[i*8+a], a=0..6
__device__ float g_m[WD];
__device__ float g_mshift[WD];            // g_mshift[t] = m[t+3]
__device__ float g_aprev[WD];
__device__ float g_out_acc;

__device__ __forceinline__ int posmod(int v, int m) {
    int r = v % m;
    return r < 0 ? r + m : r;
}

// ---------------------------------------------------------------------------
// MAIN: bx%7==0 -> W-role wr=bx/7 (wr<256: hidden partial; else contrib block
// of 4 rows, g loaded once per j feeding 4 rows -> sgrad L2 traffic /4).
// Other blocks: saog pure copy (__ldcs/__stcs; finalize fixes time slice).
// ---------------------------------------------------------------------------
__global__ void k_main(const float* __restrict__ W,
                       const float* __restrict__ state_in,
                       const float* __restrict__ sgrad,
                       float* __restrict__ out,
                       const float* __restrict__ sa_in,
                       const float* __restrict__ og_in) {
    __shared__ float sh[CHUNK * 8];
    const int tid = threadIdx.x;
    const int bx  = blockIdx.x;

    if (bx % 7 == 0) {
        const int wr = bx / 7;             // 0..767
        if (wr == 0 && tid == 0) g_out_acc = 0.f;

        if (wr < HBLK) {
            // ---- hidden partial: hidden[k] = sum_i W[i*WD+k]*state[i,k&7]
            const int kblk  = wr & 15;
            const int split = wr >> 4;
            const int k4 = kblk * 1024 + tid * 4;
            const int i0 = split * CHUNK;
            const int dbase = (tid & 1) * 4;

            for (int idx = tid; idx < CHUNK * 8; idx += 256) {
                int i = idx >> 3, d = idx & 7;
                sh[idx] = state_in[(size_t)(i0 + i) * DP1 + d];
            }
            __syncthreads();

            const float* Wp = W + (size_t)i0 * WD + k4;
            float4 acc = make_float4(0.f, 0.f, 0.f, 0.f);
#pragma unroll 8
            for (int i = 0; i < CHUNK; ++i) {
                float4 w4 = *reinterpret_cast<const float4*>(Wp + (size_t)i * WD);
                float4 sv = *reinterpret_cast<const float4*>(&sh[i * 8 + dbase]);
                acc.x = fmaf(w4.x, sv.x, acc.x);
                acc.y = fmaf(w4.y, sv.y, acc.y);
                acc.z = fmaf(w4.z, sv.z, acc.z);
                acc.w = fmaf(w4.w, sv.w, acc.w);
            }
            *reinterpret_cast<float4*>(&g_hpart[split][k4]) = acc;
        } else {
            // ---- contrib, 4 rows per block
            const int i0 = (wr - HBLK) * 4;
            const float4* gg = reinterpret_cast<const float4*>(sgrad);
            const float4* Wr0 = reinterpret_cast<const float4*>(W + (size_t)i0 * WD);

            float acc[4][7];
#pragma unroll
            for (int r = 0; r < 4; ++r)
#pragma unroll
                for (int a = 0; a < 7; ++a) acc[r][a] = 0.f;

            for (int j = tid; j < WIDTH; j += 256) {
                float4 g0 = gg[j * 2];
                float4 g1 = gg[j * 2 + 1];
#pragma unroll
                for (int r = 0; r < 4; ++r) {
                    const float4* Wr = Wr0 + (size_t)r * (WD / 4);
                    float4 w0 = Wr[j * 2];
                    float4 w1 = Wr[j * 2 + 1];
                    acc[r][0] = fmaf(w0.y, g0.y, acc[r][0]);
                    acc[r][1] = fmaf(w0.z, g0.z, acc[r][1]);
                    acc[r][2] = fmaf(w0.w, g0.w, acc[r][2]);
                    acc[r][3] = fmaf(w1.x, g1.x, acc[r][3]);
                    acc[r][4] = fmaf(w1.y, g1.y, acc[r][4]);
                    acc[r][5] = fmaf(w1.z, g1.z, acc[r][5]);
                    acc[r][6] = fmaf(w1.w, g1.w, acc[r][6]);
                }
            }
            float (*red)[4][7] = reinterpret_cast<float (*)[4][7]>(sh);
#pragma unroll
            for (int r = 0; r < 4; ++r)
#pragma unroll
                for (int a = 0; a < 7; ++a)
#pragma unroll
                    for (int off = 16; off; off >>= 1)
                        acc[r][a] += __shfl_down_sync(0xffffffffu, acc[r][a], off);
            if ((tid & 31) == 0) {
                int wwid = tid >> 5;
#pragma unroll
                for (int r = 0; r < 4; ++r)
#pragma unroll
                    for (int a = 0; a < 7; ++a) red[wwid][r][a] = acc[r][a];
            }
            __syncthreads();
            if (tid < 28) {
                int r = tid / 7, a = tid % 7;
                float s = 0.f;
#pragma unroll
                for (int wi = 0; wi < 8; ++wi) s += red[wi][r][a];
                g_contrib[(size_t)(i0 + r) * 8 + a] = s;
            }
        }
    } else {
        // ---- saog: pure dual copy, streaming both directions.
        const int sid = bx - bx / 7 - 1;   // 0..4607
        const int q = sid * 256 + tid;
        if (q >= NQ_SAOG) return;
        const int idx = 3 + 4 * q;

        const float4* sa4 = reinterpret_cast<const float4*>(sa_in);
        const float4* og4 = reinterpret_cast<const float4*>(og_in);
        float4 sA = __ldcs(sa4 + q), sB = __ldcs(sa4 + q + 1);
        float4 oA = __ldcs(og4 + q), oB = __ldcs(og4 + q + 1);

        __stcs(reinterpret_cast<float4*>(&out[OFF_SA + idx]),
               make_float4(sA.w, sB.x, sB.y, sB.z));
        __stcs(reinterpret_cast<float4*>(&out[OFF_OG + idx]),
               make_float4(oA.w, oB.x, oB.y, oB.z));

        if (q == 0) {
#pragma unroll
            for (int e = 0; e < 3; ++e) {
                out[OFF_SA + e] = sa_in[e];
                out[OFF_OG + e] = og_in[e];
            }
        }
        if (q == NQ_SAOG - 1) {
            out[OFF_SA + N_SAOG - 1] = sa_in[N_SAOG - 1];
            out[OFF_OG + N_SAOG - 1] = og_in[N_SAOG - 1];
        }
    }
#if __CUDA_ARCH__ >= 900
    cudaTriggerProgrammaticLaunchCompletion();
#endif
}

// ---------------------------------------------------------------------------
// finalize (PDL): prologue = input-only loads; sync; consume scratch + write,
// incl. the SA/OG time-slice fixup (ordered after k_main's saog stores).
// tia(a) = time + 2a - 14 (mod 242); tia==time only at a=7, (tia±1)!=time.
// ---------------------------------------------------------------------------
__global__ void k_finalize(float* __restrict__ out,
                           const float* __restrict__ x,
                           const float* __restrict__ ow,
                           const float* __restrict__ sa_in,
                           const float* __restrict__ og_in,
                           const int* __restrict__ time_p) {
    const int k = blockIdx.x * blockDim.x + threadIdx.x;   // 0..WD-1
    const int w = k >> 3, a = k & 7;
    const int time = *time_p;

    const int tia = posmod(time - 2 * DEPTH + 2 * (a + 1), TMOD);
    float rm_v = 0.f, og_v = 0.f, rg_pre = 0.f, aprev;
    const float ow_o  = ow[(size_t)w * DP1 + a + 1];
    const float ow_o0 = (a == 0) ? ow[(size_t)w * DP1] : 0.f;
    const float xv    = (a == 0) ? x[w] : 0.f;
    if (a < DEPTH - 1) {
        int t1 = (tia + 1) % TMOD;
        rm_v = sa_in[((size_t)w * DP1 + a + 2) * TMOD + t1];
        og_v = og_in[((size_t)w * DP1 + a + 1) * TMOD + tia];
        rg_pre = sa_in[((size_t)w * DP1 + a + 1) * TMOD + tia];
        aprev = sa_in[((size_t)w * DP1 + a) * TMOD + posmod(tia - 1, TMOD)];
    } else {
        aprev = sa_in[((size_t)w * DP1 + DEPTH - 1) * TMOD + posmod(time - 1, TMOD)];
    }

#if __CUDA_ARCH__ >= 900
    cudaGridDependencySynchronize();
#endif

    float h = 0.f;
#pragma unroll
    for (int c = 0; c < NSPLIT; ++c) h += g_hpart[c][k];
    float s = fmaxf(h, 0.f);

    size_t o = (size_t)w * DP1 + a + 1;
    out[OFF_STATE + o] = s;
    out[OFF_OWG + o]   = s;
    out[OFF_SA + o * TMOD + time] = s;
    out[OFF_OG + o * TMOD + time] = ow_o;
    float v = ow_o * s;
    if (a == 0) {
        size_t o0 = (size_t)w * DP1;
        out[OFF_STATE + o0] = xv;
        out[OFF_OWG   + o0] = xv;
        out[OFF_SA + o0 * TMOD + time] = xv;
        out[OFF_OG + o0 * TMOD + time] = ow_o0;
        v = fmaf(ow_o0, xv, v);
    }

    float sgv, rg;
    if (a < DEPTH - 1) {
        sgv = fmaf(rm_v > 0.f ? 1.f : 0.f, g_contrib[k], og_v);
        rg = (rg_pre > 0.f) ? 1.f : 0.f;
    } else {
        sgv = ow[(size_t)w * DP1 + DEPTH];
        rg = (s > 0.f) ? 1.f : 0.f;
    }
    out[OFF_SG + k] = sgv;
    float mval = sgv * rg;
    g_m[k] = mval;
    if (k >= 3) g_mshift[k - 3] = mval;
    g_aprev[k] = aprev;

    __shared__ float red[8];
#pragma unroll
    for (int off = 16; off; off >>= 1)
        v += __shfl_down_sync(0xffffffffu, v, off);
    if ((threadIdx.x & 31) == 0) red[threadIdx.x >> 5] = v;
    __syncthreads();
    if (threadIdx.x == 0) {
        float t = 0.f;
#pragma unroll
        for (int i = 0; i < 8; ++i) t += red[i];
        atomicAdd(&g_out_acc, t);
    }
#if __CUDA_ARCH__ >= 900
    cudaTriggerProgrammaticLaunchCompletion();
#endif
}

// ---------------------------------------------------------------------------
// grad (PDL): sync first, then block-per-row, sector-aligned via mshift,
// streaming stores (round-13 measured-best grad).
// ---------------------------------------------------------------------------
__global__ void k_grad(float* __restrict__ out) {
    const int i = blockIdx.x;
    const int tid = threadIdx.x;

#if __CUDA_ARCH__ >= 900
    cudaGridDependencySynchronize();
#endif
    if (i == 0 && tid == 0) out[OFF_OUT] = g_out_acc;

    const float* ap = g_aprev + (size_t)i * 8;
    const float4 apv = (tid & 1)
        ? make_float4(__ldg(ap + 7), __ldg(ap + 0), __ldg(ap + 1), __ldg(ap + 2))
        : make_float4(__ldg(ap + 3), __ldg(ap + 4), __ldg(ap + 5), __ldg(ap + 6));

    float* dst = out + OFF_GRAD + (size_t)i * WD;
    const float4* ms4 = reinterpret_cast<const float4*>(g_mshift);

    for (int q = tid; q < NQ_GROW; q += 256) {
        float4 mv = ms4[q];
        __stcs(reinterpret_cast<float4*>(dst + 3 + 4 * q),
               make_float4(apv.x * mv.x, apv.y * mv.y,
                           apv.z * mv.z, apv.w * mv.w));
    }
    if (tid == 0) {
        dst[0] = __ldg(ap + 0) * g_m[0];
        dst[1] = __ldg(ap + 1) * g_m[1];
        dst[2] = __ldg(ap + 2) * g_m[2];
    } else if (tid == 1) {
        dst[WD - 1] = __ldg(ap + 7) * g_m[WD - 1];
    }
}

// ---------------------------------------------------------------------------
extern "C" void kernel_launch(void* const* d_in, const int* in_sizes, int n_in,
                              void* d_out, int out_size) {
    const float* x    = (const float*)d_in[0];
    const float* W    = (const float*)d_in[1];
    const float* ow   = (const float*)d_in[2];
    const float* st   = (const float*)d_in[3];
    const float* sa   = (const float*)d_in[4];
    const float* sgr  = (const float*)d_in[5];
    const float* og   = (const float*)d_in[6];
    const int*   tim  = (const int*)d_in[7];
    float* out = (float*)d_out;

    k_main<<<MAIN_BLK, 256>>>(W, st, sgr, out, sa, og);

    cudaLaunchAttribute attr[1];
    attr[0].id = cudaLaunchAttributeProgrammaticStreamSerialization;
    attr[0].val.programmaticStreamSerializationAllowed = 1;

    {
        cudaLaunchConfig_t cfg = {};
        cfg.gridDim = dim3(WD / 256);
        cfg.blockDim = dim3(256);
        cfg.attrs = attr;
        cfg.numAttrs = 1;
        cudaLaunchKernelEx(&cfg, k_finalize, out, x, ow, sa, og, tim);
    }
    {
        cudaLaunchConfig_t cfg = {};
        cfg.gridDim = dim3(WIDTH);
        cfg.blockDim = dim3(256);
        cfg.attrs = attr;
        cfg.numAttrs = 1;
        cudaLaunchKernelEx(&cfg, k_grad, out);
    }
}

// round 17
// speedup vs baseline: 1.1144x; 1.0878x over previous
#include <cuda_runtime.h>
#include <cstdint>
#include <cstddef>

#define WIDTH  2048
#define DEPTH  8
#define DP1    9
#define TMOD   242          // 30*DEPTH + 2
#define WD     16384        // WIDTH*DEPTH
#define NSPLIT 16           // i-splits for hidden
#define CHUNK  128          // WIDTH / NSPLIT
#define HBLK   256          // hidden blocks (16 kblk x 16 split)
#define CBLK   512          // contrib blocks (4 rows each)
#define WROLES (HBLK + CBLK)        // 768

// d_out layout (float32, reference return order)
#define OFF_OUT   0ULL
#define OFF_STATE 1ULL
#define OFF_SA    18433ULL
#define OFF_SG    4478977ULL
#define OFF_OG    4495361ULL
#define OFF_GRAD  8955905ULL
#define OFF_OWG   42510337ULL

#define N_SAOG    (WIDTH * DP1 * TMOD)     // 4460544
#define NQ_SAOG   1115135                  // quads idx = 3+4q
#define SAOG_BLK  ((NQ_SAOG + 255) / 256)  // 4356
#define NQ_GROW   4095                     // per-row quads k = 3+4q

// scratch (allocation-free)
__device__ float g_hpart[NSPLIT][WD];     // hidden partials (1 MB)
__device__ float g_contrib[WD];           // contrib[i*8+a], a=0..6
__device__ float g_m[WD];
__device__ float g_mshift[WD];            // g_mshift[t] = m[t+3]
__device__ float g_aprev[WD];
__device__ float g_out_acc;

__device__ __forceinline__ int posmod(int v, int m) {
    int r = v % m;
    return r < 0 ? r + m : r;
}

// ---------------------------------------------------------------------------
// W-role kernel (register-fat is OK — it no longer shares a budget with the
// copy blocks). Triggers PDL completion AT ENTRY so k_saog launches
// immediately and runs concurrently.
// wr<256: hidden partial; else contrib block of 4 rows (g loaded once per j
// feeds 4 rows -> sgrad L2 traffic /4).
// ---------------------------------------------------------------------------
__global__ void k_wrole(const float* __restrict__ W,
                        const float* __restrict__ state_in,
                        const float* __restrict__ sgrad) {
#if __CUDA_ARCH__ >= 900
    cudaTriggerProgrammaticLaunchCompletion();
#endif
    __shared__ float sh[CHUNK * 8];
    const int tid = threadIdx.x;
    const int wr  = blockIdx.x;            // 0..767

    if (wr == 0 && tid == 0) g_out_acc = 0.f;

    if (wr < HBLK) {
        // ---- hidden partial: hidden[k] = sum_i W[i*WD+k]*state[i,k&7]
        const int kblk  = wr & 15;
        const int split = wr >> 4;
        const int k4 = kblk * 1024 + tid * 4;
        const int i0 = split * CHUNK;
        const int dbase = (tid & 1) * 4;

        for (int idx = tid; idx < CHUNK * 8; idx += 256) {
            int i = idx >> 3, d = idx & 7;
            sh[idx] = state_in[(size_t)(i0 + i) * DP1 + d];
        }
        __syncthreads();

        const float* Wp = W + (size_t)i0 * WD + k4;
        float4 acc = make_float4(0.f, 0.f, 0.f, 0.f);
#pragma unroll 8
        for (int i = 0; i < CHUNK; ++i) {
            float4 w4 = *reinterpret_cast<const float4*>(Wp + (size_t)i * WD);
            float4 sv = *reinterpret_cast<const float4*>(&sh[i * 8 + dbase]);
            acc.x = fmaf(w4.x, sv.x, acc.x);
            acc.y = fmaf(w4.y, sv.y, acc.y);
            acc.z = fmaf(w4.z, sv.z, acc.z);
            acc.w = fmaf(w4.w, sv.w, acc.w);
        }
        *reinterpret_cast<float4*>(&g_hpart[split][k4]) = acc;
    } else {
        // ---- contrib, 4 rows per block
        const int i0 = (wr - HBLK) * 4;
        const float4* gg = reinterpret_cast<const float4*>(sgrad);
        const float4* Wr0 = reinterpret_cast<const float4*>(W + (size_t)i0 * WD);

        float acc[4][7];
#pragma unroll
        for (int r = 0; r < 4; ++r)
#pragma unroll
            for (int a = 0; a < 7; ++a) acc[r][a] = 0.f;

        for (int j = tid; j < WIDTH; j += 256) {
            float4 g0 = gg[j * 2];
            float4 g1 = gg[j * 2 + 1];
#pragma unroll
            for (int r = 0; r < 4; ++r) {
                const float4* Wr = Wr0 + (size_t)r * (WD / 4);
                float4 w0 = Wr[j * 2];
                float4 w1 = Wr[j * 2 + 1];
                acc[r][0] = fmaf(w0.y, g0.y, acc[r][0]);
                acc[r][1] = fmaf(w0.z, g0.z, acc[r][1]);
                acc[r][2] = fmaf(w0.w, g0.w, acc[r][2]);
                acc[r][3] = fmaf(w1.x, g1.x, acc[r][3]);
                acc[r][4] = fmaf(w1.y, g1.y, acc[r][4]);
                acc[r][5] = fmaf(w1.z, g1.z, acc[r][5]);
                acc[r][6] = fmaf(w1.w, g1.w, acc[r][6]);
            }
        }
        float (*red)[4][7] = reinterpret_cast<float (*)[4][7]>(sh);
#pragma unroll
        for (int r = 0; r < 4; ++r)
#pragma unroll
            for (int a = 0; a < 7; ++a)
#pragma unroll
                for (int off = 16; off; off >>= 1)
                    acc[r][a] += __shfl_down_sync(0xffffffffu, acc[r][a], off);
        if ((tid & 31) == 0) {
            int wwid = tid >> 5;
#pragma unroll
            for (int r = 0; r < 4; ++r)
#pragma unroll
                for (int a = 0; a < 7; ++a) red[wwid][r][a] = acc[r][a];
        }
        __syncthreads();
        if (tid < 28) {
            int r = tid / 7, a = tid % 7;
            float s = 0.f;
#pragma unroll
            for (int wi = 0; wi < 8; ++wi) s += red[wi][r][a];
            g_contrib[(size_t)(i0 + r) * 8 + a] = s;
        }
    }
}

// ---------------------------------------------------------------------------
// saog copy kernel (PDL secondary, NO grid sync — independent of k_wrole, so
// it runs concurrently). Lean registers -> high occupancy -> MLP for the
// copy stream. Streaming ld/st keeps it out of wrole's L2 working set.
// ---------------------------------------------------------------------------
__global__ void k_saog(float* __restrict__ out,
                       const float* __restrict__ sa_in,
                       const float* __restrict__ og_in) {
    const int q = blockIdx.x * 256 + threadIdx.x;
    if (q >= NQ_SAOG) return;
    const int idx = 3 + 4 * q;

    const float4* sa4 = reinterpret_cast<const float4*>(sa_in);
    const float4* og4 = reinterpret_cast<const float4*>(og_in);
    float4 sA = __ldcs(sa4 + q), sB = __ldcs(sa4 + q + 1);
    float4 oA = __ldcs(og4 + q), oB = __ldcs(og4 + q + 1);

    __stcs(reinterpret_cast<float4*>(&out[OFF_SA + idx]),
           make_float4(sA.w, sB.x, sB.y, sB.z));
    __stcs(reinterpret_cast<float4*>(&out[OFF_OG + idx]),
           make_float4(oA.w, oB.x, oB.y, oB.z));

    if (q == 0) {
#pragma unroll
        for (int e = 0; e < 3; ++e) {
            out[OFF_SA + e] = sa_in[e];
            out[OFF_OG + e] = og_in[e];
        }
    }
    if (q == NQ_SAOG - 1) {
        out[OFF_SA + N_SAOG - 1] = sa_in[N_SAOG - 1];
        out[OFF_OG + N_SAOG - 1] = og_in[N_SAOG - 1];
    }
#if __CUDA_ARCH__ >= 900
    cudaTriggerProgrammaticLaunchCompletion();
#endif
}

// ---------------------------------------------------------------------------
// finalize (PDL): prologue = input-only loads; grid sync (waits on ALL prior
// in-stream grids: wrole AND saog); consume scratch + write, incl. the SA/OG
// time-slice fixup ordered after saog's stores.
// tia(a) = time + 2a - 14 (mod 242); tia==time only at a=7, (tia±1)!=time.
// ---------------------------------------------------------------------------
__global__ void k_finalize(float* __restrict__ out,
                           const float* __restrict__ x,
                           const float* __restrict__ ow,
                           const float* __restrict__ sa_in,
                           const float* __restrict__ og_in,
                           const int* __restrict__ time_p) {
    const int k = blockIdx.x * blockDim.x + threadIdx.x;   // 0..WD-1
    const int w = k >> 3, a = k & 7;
    const int time = *time_p;

    const int tia = posmod(time - 2 * DEPTH + 2 * (a + 1), TMOD);
    float rm_v = 0.f, og_v = 0.f, rg_pre = 0.f, aprev;
    const float ow_o  = ow[(size_t)w * DP1 + a + 1];
    const float ow_o0 = (a == 0) ? ow[(size_t)w * DP1] : 0.f;
    const float xv    = (a == 0) ? x[w] : 0.f;
    if (a < DEPTH - 1) {
        int t1 = (tia + 1) % TMOD;
        rm_v = sa_in[((size_t)w * DP1 + a + 2) * TMOD + t1];
        og_v = og_in[((size_t)w * DP1 + a + 1) * TMOD + tia];
        rg_pre = sa_in[((size_t)w * DP1 + a + 1) * TMOD + tia];
        aprev = sa_in[((size_t)w * DP1 + a) * TMOD + posmod(tia - 1, TMOD)];
    } else {
        aprev = sa_in[((size_t)w * DP1 + DEPTH - 1) * TMOD + posmod(time - 1, TMOD)];
    }

#if __CUDA_ARCH__ >= 900
    cudaGridDependencySynchronize();
#endif

    float h = 0.f;
#pragma unroll
    for (int c = 0; c < NSPLIT; ++c) h += g_hpart[c][k];
    float s = fmaxf(h, 0.f);

    size_t o = (size_t)w * DP1 + a + 1;
    out[OFF_STATE + o] = s;
    out[OFF_OWG + o]   = s;
    out[OFF_SA + o * TMOD + time] = s;
    out[OFF_OG + o * TMOD + time] = ow_o;
    float v = ow_o * s;
    if (a == 0) {
        size_t o0 = (size_t)w * DP1;
        out[OFF_STATE + o0] = xv;
        out[OFF_OWG   + o0] = xv;
        out[OFF_SA + o0 * TMOD + time] = xv;
        out[OFF_OG + o0 * TMOD + time] = ow_o0;
        v = fmaf(ow_o0, xv, v);
    }

    float sgv, rg;
    if (a < DEPTH - 1) {
        sgv = fmaf(rm_v > 0.f ? 1.f : 0.f, g_contrib[k], og_v);
        rg = (rg_pre > 0.f) ? 1.f : 0.f;
    } else {
        sgv = ow[(size_t)w * DP1 + DEPTH];
        rg = (s > 0.f) ? 1.f : 0.f;
    }
    out[OFF_SG + k] = sgv;
    float mval = sgv * rg;
    g_m[k] = mval;
    if (k >= 3) g_mshift[k - 3] = mval;
    g_aprev[k] = aprev;

    __shared__ float red[8];
#pragma unroll
    for (int off = 16; off; off >>= 1)
        v += __shfl_down_sync(0xffffffffu, v, off);
    if ((threadIdx.x & 31) == 0) red[threadIdx.x >> 5] = v;
    __syncthreads();
    if (threadIdx.x == 0) {
        float t = 0.f;
#pragma unroll
        for (int i = 0; i < 8; ++i) t += red[i];
        atomicAdd(&g_out_acc, t);
    }
#if __CUDA_ARCH__ >= 900
    cudaTriggerProgrammaticLaunchCompletion();
#endif
}

// ---------------------------------------------------------------------------
// grad (PDL): sync first, then block-per-row, sector-aligned via mshift,
// streaming stores (measured-best grad scheme).
// ---------------------------------------------------------------------------
__global__ void k_grad(float* __restrict__ out) {
    const int i = blockIdx.x;
    const int tid = threadIdx.x;

#if __CUDA_ARCH__ >= 900
    cudaGridDependencySynchronize();
#endif
    if (i == 0 && tid == 0) out[OFF_OUT] = g_out_acc;

    const float* ap = g_aprev + (size_t)i * 8;
    const float4 apv = (tid & 1)
        ? make_float4(__ldg(ap + 7), __ldg(ap + 0), __ldg(ap + 1), __ldg(ap + 2))
        : make_float4(__ldg(ap + 3), __ldg(ap + 4), __ldg(ap + 5), __ldg(ap + 6));

    float* dst = out + OFF_GRAD + (size_t)i * WD;
    const float4* ms4 = reinterpret_cast<const float4*>(g_mshift);

    for (int q = tid; q < NQ_GROW; q += 256) {
        float4 mv = ms4[q];
        __stcs(reinterpret_cast<float4*>(dst + 3 + 4 * q),
               make_float4(apv.x * mv.x, apv.y * mv.y,
                           apv.z * mv.z, apv.w * mv.w));
    }
    if (tid == 0) {
        dst[0] = __ldg(ap + 0) * g_m[0];
        dst[1] = __ldg(ap + 1) * g_m[1];
        dst[2] = __ldg(ap + 2) * g_m[2];
    } else if (tid == 1) {
        dst[WD - 1] = __ldg(ap + 7) * g_m[WD - 1];
    }
}

// ---------------------------------------------------------------------------
extern "C" void kernel_launch(void* const* d_in, const int* in_sizes, int n_in,
                              void* d_out, int out_size) {
    const float* x    = (const float*)d_in[0];
    const float* W    = (const float*)d_in[1];
    const float* ow   = (const float*)d_in[2];
    const float* st   = (const float*)d_in[3];
    const float* sa   = (const float*)d_in[4];
    const float* sgr  = (const float*)d_in[5];
    const float* og   = (const float*)d_in[6];
    const int*   tim  = (const int*)d_in[7];
    float* out = (float*)d_out;

    k_wrole<<<WROLES, 256>>>(W, st, sgr);

    cudaLaunchAttribute attr[1];
    attr[0].id = cudaLaunchAttributeProgrammaticStreamSerialization;
    attr[0].val.programmaticStreamSerializationAllowed = 1;

    {
        // launches as soon as k_wrole's entry-trigger fires -> concurrent
        cudaLaunchConfig_t cfg = {};
        cfg.gridDim = dim3(SAOG_BLK);
        cfg.blockDim = dim3(256);
        cfg.attrs = attr;
        cfg.numAttrs = 1;
        cudaLaunchKernelEx(&cfg, k_saog, out, sa, og);
    }
    {
        cudaLaunchConfig_t cfg = {};
        cfg.gridDim = dim3(WD / 256);
        cfg.blockDim = dim3(256);
        cfg.attrs = attr;
        cfg.numAttrs = 1;
        cudaLaunchKernelEx(&cfg, k_finalize, out, x, ow, sa, og, tim);
    }
    {
        cudaLaunchConfig_t cfg = {};
        cfg.gridDim = dim3(WIDTH);
        cfg.blockDim = dim3(256);
        cfg.attrs = attr;
        cfg.numAttrs = 1;
        cudaLaunchKernelEx(&cfg, k_grad, out);
    }
}